// round 10
// baseline (speedup 1.0000x reference)
#include <cuda_runtime.h>
#include <cuda_fp16.h>
#include <math.h>

#define N_NODES 50000
#define N_EDGES 1600000
#define N_HEADS 8
#define IN_DIM  512
#define OUT_DIM 64
#define FEAT_DIM 512   // N_HEADS * OUT_DIM
#define LRELU_ALPHA 0.2f
#define SCAN_NB 49     // ceil(50000 / 1024)

// ---------------- scratch (device globals; no allocation allowed) -----------
__device__ __half g_xh[N_NODES * IN_DIM];        // 51.2 MB fp16 copy of x
__device__ __half g_wh[FEAT_DIM * IN_DIM];       // 0.5 MB  B^T[j][k] fp16
__device__ __half g_feath[N_NODES * FEAT_DIM];   // 51.2 MB (gather source, fp16)
__device__ float g_alpha_s[N_NODES * N_HEADS];
__device__ float g_alpha_d[N_NODES * N_HEADS];
__device__ int   g_deg[N_NODES];
__device__ int   g_cursor[N_NODES];
__device__ int   g_rowstart[N_NODES + 1];
__device__ int   g_csr_dst[N_EDGES];
__device__ int   g_bsum[64];
__device__ int   g_boff[64];

// ---------------- zero counters + alpha accumulators -------------------------
__global__ void zero_kernel() {
    int i = blockIdx.x * blockDim.x + threadIdx.x;
    int stride = gridDim.x * blockDim.x;
    for (int j = i; j < N_NODES * N_HEADS; j += stride) {
        g_alpha_s[j] = 0.f;
        g_alpha_d[j] = 0.f;
    }
    for (int j = i; j < N_NODES; j += stride) {
        g_deg[j] = 0;
        g_cursor[j] = 0;
    }
}

// ---------------- input conversion: x -> fp16, W -> B^T[j][k] fp16 -----------
__global__ __launch_bounds__(256) void conv_x_kernel(const float* __restrict__ x) {
    int i = blockIdx.x * blockDim.x + threadIdx.x;
    int stride = gridDim.x * blockDim.x;
    const int n4 = N_NODES * IN_DIM / 4;
    for (int j = i; j < n4; j += stride) {
        float4 v = *(const float4*)(x + j * 4);
        __half2* o = (__half2*)(g_xh + j * 4);
        o[0] = __floats2half2_rn(v.x, v.y);
        o[1] = __floats2half2_rn(v.z, v.w);
    }
}

__global__ __launch_bounds__(256) void conv_w_kernel(const float* __restrict__ W) {
    int i = blockIdx.x * blockDim.x + threadIdx.x;     // over 512*512
    int j = i >> 9, k = i & 511;                       // j = global out col
    int h = j >> 6, o = j & 63;
    g_wh[j * IN_DIM + k] = __float2half_rn(W[((long)h * IN_DIM + k) * OUT_DIM + o]);
}

// ---------------- fp16 tensor-core GEMM: feat = x @ W (+ fused alpha) --------
// A = g_xh [node][k], B^T = g_wh [j][k]; mma.m16n8k16 via ldmatrix.
// BM=128, BN=128, BK=32; 8 warps x (64x32); 3-stage cp.async pipeline.
#define GEMM_BM 128
#define GEMM_BN 128
#define GEMM_BK 32
#define GEMM_STAGES 3
#define TILE_ROW_H 40                          // halves per smem row (80 B)
#define TILE_BYTES (128 * TILE_ROW_H * 2)      // 10240 per tile
#define GEMM_SMEM_BYTES (GEMM_STAGES * 2 * TILE_BYTES)   // 61440

__device__ __forceinline__ void ldsm_x4(unsigned* r, unsigned addr) {
    asm volatile("ldmatrix.sync.aligned.m8n8.x4.shared.b16 {%0,%1,%2,%3}, [%4];"
                 : "=r"(r[0]), "=r"(r[1]), "=r"(r[2]), "=r"(r[3]) : "r"(addr));
}

__device__ __forceinline__ void mma_fp16(float* c, const unsigned* a,
                                         unsigned b0, unsigned b1) {
    asm volatile(
        "mma.sync.aligned.m16n8k16.row.col.f32.f16.f16.f32 "
        "{%0,%1,%2,%3},{%4,%5,%6,%7},{%8,%9},{%0,%1,%2,%3};"
        : "+f"(c[0]), "+f"(c[1]), "+f"(c[2]), "+f"(c[3])
        : "r"(a[0]), "r"(a[1]), "r"(a[2]), "r"(a[3]), "r"(b0), "r"(b1));
}

__device__ __forceinline__ void cp_async16(unsigned saddr, const void* g, int srcbytes) {
    asm volatile("cp.async.cg.shared.global [%0], [%1], 16, %2;\n"
                 :: "r"(saddr), "l"(g), "r"(srcbytes));
}
__device__ __forceinline__ void cp_commit() {
    asm volatile("cp.async.commit_group;\n");
}
__device__ __forceinline__ void cp_wait1() {
    asm volatile("cp.async.wait_group 1;\n");
}

__global__ __launch_bounds__(256) void gemm_fp16_kernel(const float* __restrict__ att_w) {
    extern __shared__ __half hsm[];
    unsigned sA = (unsigned)__cvta_generic_to_shared(hsm);
    unsigned sB = sA + GEMM_STAGES * TILE_BYTES;

    const int t    = threadIdx.x;
    const int lane = t & 31;
    const int wid  = t >> 5;
    const int row0 = blockIdx.y * GEMM_BM;
    const int col0 = blockIdx.x * GEMM_BN;

    const int wm = (wid & 1) * 64;
    const int wn = (wid >> 1) * 32;
    const int fr = lane >> 2;   // 0..7
    const int fc = lane & 3;    // 0..3

    // ---- cp.async mapping: 2 x 16B chunks per thread for each of A, B ----
    int crow[2], ckc[2], avalid[2];
    const __half* aptr[2];
    const __half* bptr[2];
#pragma unroll
    for (int i = 0; i < 2; i++) {
        int chunk = t + 256 * i;       // 0..511
        crow[i] = chunk >> 2;          // 0..127
        ckc[i]  = chunk & 3;           // 16B chunk within 64B row
        int gr  = row0 + crow[i];
        avalid[i] = (gr < N_NODES) ? 16 : 0;
        aptr[i] = g_xh + (long)gr * IN_DIM + ckc[i] * 8;
        bptr[i] = g_wh + (long)(col0 + crow[i]) * IN_DIM + ckc[i] * 8;
    }

    float acc[4][4][4];
#pragma unroll
    for (int mt = 0; mt < 4; mt++)
#pragma unroll
        for (int nt = 0; nt < 4; nt++)
#pragma unroll
            for (int i = 0; i < 4; i++) acc[mt][nt][i] = 0.f;

    const int NKT = IN_DIM / GEMM_BK;   // 16

    auto issue_tile = [&](int s, int buf) {
        int koff = s * GEMM_BK;
#pragma unroll
        for (int i = 0; i < 2; i++) {
            unsigned off = buf * TILE_BYTES + crow[i] * (TILE_ROW_H * 2) + ckc[i] * 16;
            cp_async16(sA + off, aptr[i] + koff, avalid[i]);
            cp_async16(sB + off, bptr[i] + koff, 16);
        }
        cp_commit();
    };

    // per-lane ldmatrix base addresses (row-major tiles, k-contiguous)
    unsigned aaddr0 = sA + (wm + (lane & 15)) * (TILE_ROW_H * 2) + (lane >> 4) * 16;
    unsigned baddr0 = sB + (wn + (lane & 15)) * (TILE_ROW_H * 2) + (lane >> 4) * 16;

    issue_tile(0, 0);
    issue_tile(1, 1);

    for (int kt = 0; kt < NKT; kt++) {
        cp_wait1();               // tile kt resident
        __syncthreads();          // all threads done with recycled buffer

        if (kt + 2 < NKT) issue_tile(kt + 2, (kt + 2) % GEMM_STAGES);
        else              cp_commit();   // dummy group keeps wait_group 1 uniform

        unsigned stoff = (kt % GEMM_STAGES) * TILE_BYTES;
#pragma unroll
        for (int ks = 0; ks < 2; ks++) {          // two k16 steps per BK=32
            unsigned a[4][4], b[2][4];
#pragma unroll
            for (int mt = 0; mt < 4; mt++)
                ldsm_x4(a[mt], aaddr0 + stoff + mt * (16 * TILE_ROW_H * 2) + ks * 32);
#pragma unroll
            for (int np = 0; np < 2; np++)
                ldsm_x4(b[np], baddr0 + stoff + np * (16 * TILE_ROW_H * 2) + ks * 32);
#pragma unroll
            for (int mt = 0; mt < 4; mt++) {
                mma_fp16(acc[mt][0], a[mt], b[0][0], b[0][2]);
                mma_fp16(acc[mt][1], a[mt], b[0][1], b[0][3]);
                mma_fp16(acc[mt][2], a[mt], b[1][0], b[1][2]);
                mma_fp16(acc[mt][3], a[mt], b[1][1], b[1][3]);
            }
        }
    }

    // ---- epilogue: store feat as fp16 ----
#pragma unroll
    for (int mt = 0; mt < 4; mt++) {
#pragma unroll
        for (int nt = 0; nt < 4; nt++) {
            int row = row0 + wm + mt * 16 + fr;
            int col = col0 + wn + nt * 8 + 2 * fc;
            if (row < N_NODES)
                *(__half2*)&g_feath[(long)row * FEAT_DIM + col] =
                    __floats2half2_rn(acc[mt][nt][0], acc[mt][nt][1]);
            if (row + 8 < N_NODES)
                *(__half2*)&g_feath[(long)(row + 8) * FEAT_DIM + col] =
                    __floats2half2_rn(acc[mt][nt][2], acc[mt][nt][3]);
        }
    }

    // ---- epilogue: fused alpha partial dots ----
    {
        int head = (col0 + wn) >> 6;
        const float* a1 = att_w + head * (2 * OUT_DIM);
        const float* a2 = a1 + OUT_DIM;
        float s1[8], s2[8];
#pragma unroll
        for (int i = 0; i < 8; i++) { s1[i] = 0.f; s2[i] = 0.f; }
#pragma unroll
        for (int nt = 0; nt < 4; nt++) {
            int o = (wn & 63) + nt * 8 + 2 * fc;
            float w10 = a1[o], w11 = a1[o + 1];
            float w20 = a2[o], w21 = a2[o + 1];
#pragma unroll
            for (int mt = 0; mt < 4; mt++) {
                s1[mt*2]   = fmaf(acc[mt][nt][0], w10, fmaf(acc[mt][nt][1], w11, s1[mt*2]));
                s1[mt*2+1] = fmaf(acc[mt][nt][2], w10, fmaf(acc[mt][nt][3], w11, s1[mt*2+1]));
                s2[mt*2]   = fmaf(acc[mt][nt][0], w20, fmaf(acc[mt][nt][1], w21, s2[mt*2]));
                s2[mt*2+1] = fmaf(acc[mt][nt][2], w20, fmaf(acc[mt][nt][3], w21, s2[mt*2+1]));
            }
        }
#pragma unroll
        for (int i = 0; i < 8; i++) {
            s1[i] += __shfl_xor_sync(0xffffffffu, s1[i], 1);
            s1[i] += __shfl_xor_sync(0xffffffffu, s1[i], 2);
            s2[i] += __shfl_xor_sync(0xffffffffu, s2[i], 1);
            s2[i] += __shfl_xor_sync(0xffffffffu, s2[i], 2);
        }
        if (fc == 0) {
#pragma unroll
            for (int i = 0; i < 8; i++) {
                int row = row0 + wm + (i >> 1) * 16 + fr + (i & 1) * 8;
                if (row < N_NODES) {
                    atomicAdd(&g_alpha_s[row * N_HEADS + head], s1[i]);
                    atomicAdd(&g_alpha_d[row * N_HEADS + head], s2[i]);
                }
            }
        }
    }
}

// ---------------- CSR construction -------------------------------------------
__global__ void count_kernel(const int* __restrict__ src) {
    int e = blockIdx.x * blockDim.x + threadIdx.x;
    if (e < N_EDGES) atomicAdd(&g_deg[src[e]], 1);
}

// 3-phase scan: block-local scan -> scan of block sums -> add offsets
__global__ __launch_bounds__(1024) void scan1_kernel() {
    __shared__ int wsum[32];
    int tid = threadIdx.x, b = blockIdx.x;
    int i = b * 1024 + tid;
    int lane = tid & 31, wp = tid >> 5;
    int v = (i < N_NODES) ? g_deg[i] : 0;
    int x = v;
#pragma unroll
    for (int off = 1; off < 32; off <<= 1) {
        int y = __shfl_up_sync(0xffffffffu, x, off);
        if (lane >= off) x += y;
    }
    if (lane == 31) wsum[wp] = x;
    __syncthreads();
    if (wp == 0) {
        int s = wsum[lane];
#pragma unroll
        for (int off = 1; off < 32; off <<= 1) {
            int y = __shfl_up_sync(0xffffffffu, s, off);
            if (lane >= off) s += y;
        }
        wsum[lane] = s;
    }
    __syncthreads();
    int incl = x + (wp ? wsum[wp - 1] : 0);
    if (i < N_NODES) g_rowstart[i] = incl - v;   // block-local exclusive
    if (tid == 1023) g_bsum[b] = incl;
}

__global__ void scan2_kernel() {   // 1 block, 64 threads, SCAN_NB=49 sums
    __shared__ int t0;
    int tid = threadIdx.x, lane = tid & 31, wp = tid >> 5;
    int v = (tid < SCAN_NB) ? g_bsum[tid] : 0;
    int x = v;
#pragma unroll
    for (int off = 1; off < 32; off <<= 1) {
        int y = __shfl_up_sync(0xffffffffu, x, off);
        if (lane >= off) x += y;
    }
    if (wp == 0 && lane == 31) t0 = x;
    __syncthreads();
    int incl = x + (wp ? t0 : 0);
    if (tid < SCAN_NB) g_boff[tid] = incl - v;
    if (tid == SCAN_NB - 1) g_rowstart[N_NODES] = incl;
}

__global__ __launch_bounds__(1024) void scan3_kernel() {
    int i = blockIdx.x * 1024 + threadIdx.x;
    if (i < N_NODES) g_rowstart[i] += g_boff[blockIdx.x];
}

__global__ void fill_kernel(const int* __restrict__ src, const int* __restrict__ dst) {
    int e = blockIdx.x * blockDim.x + threadIdx.x;
    if (e < N_EDGES) {
        int s = src[e];
        int p = atomicAdd(&g_cursor[s], 1);
        g_csr_dst[g_rowstart[s] + p] = dst[e];
    }
}

// ---------------- per-node softmax + aggregation (fp16 gather) ---------------
// one block (256 threads = 8 warps) per src node
__global__ __launch_bounds__(256) void agg_kernel(float* __restrict__ out) {
    int n   = blockIdx.x;
    int tid = threadIdx.x;
    int rs  = g_rowstart[n];
    int deg = g_rowstart[n + 1] - rs;

    __shared__ float s_as[N_HEADS];
    __shared__ float s_inv[N_HEADS];
    __shared__ int   s_d[32];
    __shared__ float s_att[32 * N_HEADS];

    // ---- phase A: per-head exp-sum (warp w = head w); logits are O(±6), safe
    int w = tid >> 5, l = tid & 31;
    float as = g_alpha_s[n * N_HEADS + w];
    float s = 0.f;
    for (int e = l; e < deg; e += 32) {
        int d = g_csr_dst[rs + e];
        float v = as + g_alpha_d[d * N_HEADS + w];
        v = (v > 0.f) ? v : LRELU_ALPHA * v;
        s += __expf(v);
    }
#pragma unroll
    for (int o = 16; o; o >>= 1) s += __shfl_xor_sync(0xffffffffu, s, o);
    if (l == 0) {
        s_as[w]  = as;
        s_inv[w] = (deg > 0) ? (1.0f / s) : 0.f;
    }
    __syncthreads();

    // ---- phase B: weighted gather-accumulate (half2, 4B/thread/edge) ----
    float2 acc = make_float2(0.f, 0.f);
    const __half2* fh = (const __half2*)g_feath;
    int hh = tid >> 5;                    // head for columns [tid*2, tid*2+1]

    for (int c = 0; c < deg; c += 32) {
        int len = min(32, deg - c);
        __syncthreads();                  // protect s_d/s_att reuse
        if (tid < len) s_d[tid] = g_csr_dst[rs + c + tid];
        __syncthreads();
        {
            int i = tid >> 3, h = tid & 7;
            if (i < len) {
                int d = s_d[i];
                float v = s_as[h] + g_alpha_d[d * N_HEADS + h];
                v = (v > 0.f) ? v : LRELU_ALPHA * v;
                s_att[i * 8 + h] = __expf(v) * s_inv[h];
            }
        }
        __syncthreads();
        if (len == 32) {
            // compile-time bound -> unroll -> front-batched independent LDGs
#pragma unroll 8
            for (int i = 0; i < 32; i++) {
                int d = s_d[i];
                float a = s_att[i * 8 + hh];
                float2 f = __half22float2(__ldg(&fh[(long)d * (FEAT_DIM / 2) + tid]));
                acc.x = fmaf(a, f.x, acc.x);
                acc.y = fmaf(a, f.y, acc.y);
            }
        } else {
            for (int i = 0; i < len; i++) {
                int d = s_d[i];
                float a = s_att[i * 8 + hh];
                float2 f = __half22float2(__ldg(&fh[(long)d * (FEAT_DIM / 2) + tid]));
                acc.x = fmaf(a, f.x, acc.x);
                acc.y = fmaf(a, f.y, acc.y);
            }
        }
    }

    float2* o2 = (float2*)out;
    o2[(long)n * (FEAT_DIM / 2) + tid] =
        make_float2(fmaxf(acc.x, 0.f), fmaxf(acc.y, 0.f));
}

// ---------------- launch ------------------------------------------------------
extern "C" void kernel_launch(void* const* d_in, const int* in_sizes, int n_in,
                              void* d_out, int out_size) {
    const float* x     = (const float*)d_in[0];
    const float* W     = (const float*)d_in[1];
    const float* att_w = (const float*)d_in[2];
    const int*   src   = (const int*)d_in[3];
    const int*   dst   = (const int*)d_in[4];
    float* out = (float*)d_out;

    cudaFuncSetAttribute(gemm_fp16_kernel,
                         cudaFuncAttributeMaxDynamicSharedMemorySize, GEMM_SMEM_BYTES);

    zero_kernel<<<512, 256>>>();
    conv_x_kernel<<<2048, 256>>>(x);
    conv_w_kernel<<<(FEAT_DIM * IN_DIM) / 256, 256>>>(W);
    gemm_fp16_kernel<<<dim3(FEAT_DIM / GEMM_BN, (N_NODES + GEMM_BM - 1) / GEMM_BM),
                      256, GEMM_SMEM_BYTES>>>(att_w);
    count_kernel<<<(N_EDGES + 255) / 256, 256>>>(src);
    scan1_kernel<<<SCAN_NB, 1024>>>();
    scan2_kernel<<<1, 64>>>();
    scan3_kernel<<<SCAN_NB, 1024>>>();
    fill_kernel<<<(N_EDGES + 255) / 256, 256>>>(src, dst);
    agg_kernel<<<N_NODES, 256>>>(out);
}

// round 11
// speedup vs baseline: 1.0335x; 1.0335x over previous
#include <cuda_runtime.h>
#include <cuda_fp16.h>
#include <math.h>

#define N_NODES 50000
#define N_EDGES 1600000
#define N_HEADS 8
#define IN_DIM  512
#define OUT_DIM 64
#define FEAT_DIM 512   // N_HEADS * OUT_DIM
#define LRELU_ALPHA 0.2f
#define SCAN_NB 49     // ceil(50000 / 1024)

// ---------------- scratch (device globals; no allocation allowed) -----------
__device__ __half g_xh[N_NODES * IN_DIM];        // 51.2 MB fp16 copy of x
__device__ __half g_wh[FEAT_DIM * IN_DIM];       // 0.5 MB  B^T[j][k] fp16
__device__ __half g_feath[N_NODES * FEAT_DIM];   // 51.2 MB (gather source, fp16)
__device__ float g_alpha_s[N_NODES * N_HEADS];
__device__ float g_alpha_d[N_NODES * N_HEADS];
__device__ int   g_deg[N_NODES];
__device__ int   g_cursor[N_NODES];
__device__ int   g_rowstart[N_NODES + 1];
__device__ int   g_csr_dst[N_EDGES];
__device__ int   g_bsum[64];
__device__ int   g_boff[64];

// ---------------- fused prep: zero counters/alpha + x->fp16 + W->B^T fp16 ----
__global__ __launch_bounds__(256) void prep_kernel(const float* __restrict__ x,
                                                   const float* __restrict__ W) {
    int i = blockIdx.x * blockDim.x + threadIdx.x;
    int stride = gridDim.x * blockDim.x;
    // zero alpha accumulators
    for (int j = i; j < N_NODES * N_HEADS; j += stride) {
        g_alpha_s[j] = 0.f;
        g_alpha_d[j] = 0.f;
    }
    // zero deg/cursor
    for (int j = i; j < N_NODES; j += stride) {
        g_deg[j] = 0;
        g_cursor[j] = 0;
    }
    // x -> fp16 (float4 granularity)
    const int n4 = N_NODES * IN_DIM / 4;
    for (int j = i; j < n4; j += stride) {
        float4 v = *(const float4*)(x + j * 4);
        __half2* o = (__half2*)(g_xh + j * 4);
        o[0] = __floats2half2_rn(v.x, v.y);
        o[1] = __floats2half2_rn(v.z, v.w);
    }
    // W -> B^T[j][k] fp16
    for (int p = i; p < FEAT_DIM * IN_DIM; p += stride) {
        int j = p >> 9, k = p & 511;
        int h = j >> 6, o = j & 63;
        g_wh[j * IN_DIM + k] = __float2half_rn(W[((long)h * IN_DIM + k) * OUT_DIM + o]);
    }
}

// ---------------- fp16 tensor-core GEMM: feat = x @ W (+ fused alpha) --------
// A = g_xh [node][k], B^T = g_wh [j][k]; mma.m16n8k16 via ldmatrix.
// BM=128, BN=128, BK=32; 8 warps x (64x32); 4-stage cp.async pipeline.
#define GEMM_BM 128
#define GEMM_BN 128
#define GEMM_BK 32
#define GEMM_STAGES 4
#define TILE_ROW_H 40                          // halves per smem row (80 B)
#define TILE_BYTES (128 * TILE_ROW_H * 2)      // 10240 per tile
#define GEMM_SMEM_BYTES (GEMM_STAGES * 2 * TILE_BYTES)   // 81920

__device__ __forceinline__ void ldsm_x4(unsigned* r, unsigned addr) {
    asm volatile("ldmatrix.sync.aligned.m8n8.x4.shared.b16 {%0,%1,%2,%3}, [%4];"
                 : "=r"(r[0]), "=r"(r[1]), "=r"(r[2]), "=r"(r[3]) : "r"(addr));
}

__device__ __forceinline__ void mma_fp16(float* c, const unsigned* a,
                                         unsigned b0, unsigned b1) {
    asm volatile(
        "mma.sync.aligned.m16n8k16.row.col.f32.f16.f16.f32 "
        "{%0,%1,%2,%3},{%4,%5,%6,%7},{%8,%9},{%0,%1,%2,%3};"
        : "+f"(c[0]), "+f"(c[1]), "+f"(c[2]), "+f"(c[3])
        : "r"(a[0]), "r"(a[1]), "r"(a[2]), "r"(a[3]), "r"(b0), "r"(b1));
}

__device__ __forceinline__ void cp_async16(unsigned saddr, const void* g, int srcbytes) {
    asm volatile("cp.async.cg.shared.global [%0], [%1], 16, %2;\n"
                 :: "r"(saddr), "l"(g), "r"(srcbytes));
}
__device__ __forceinline__ void cp_commit() {
    asm volatile("cp.async.commit_group;\n");
}
__device__ __forceinline__ void cp_wait2() {
    asm volatile("cp.async.wait_group 2;\n");
}

__global__ __launch_bounds__(256) void gemm_fp16_kernel(const float* __restrict__ att_w) {
    extern __shared__ __half hsm[];
    unsigned sA = (unsigned)__cvta_generic_to_shared(hsm);
    unsigned sB = sA + GEMM_STAGES * TILE_BYTES;

    const int t    = threadIdx.x;
    const int lane = t & 31;
    const int wid  = t >> 5;
    const int row0 = blockIdx.y * GEMM_BM;
    const int col0 = blockIdx.x * GEMM_BN;

    const int wm = (wid & 1) * 64;
    const int wn = (wid >> 1) * 32;
    const int fr = lane >> 2;   // 0..7
    const int fc = lane & 3;    // 0..3

    // ---- cp.async mapping: 2 x 16B chunks per thread for each of A, B ----
    int crow[2], ckc[2], avalid[2];
    const __half* aptr[2];
    const __half* bptr[2];
#pragma unroll
    for (int i = 0; i < 2; i++) {
        int chunk = t + 256 * i;       // 0..511
        crow[i] = chunk >> 2;          // 0..127
        ckc[i]  = chunk & 3;           // 16B chunk within 64B row
        int gr  = row0 + crow[i];
        avalid[i] = (gr < N_NODES) ? 16 : 0;
        aptr[i] = g_xh + (long)gr * IN_DIM + ckc[i] * 8;
        bptr[i] = g_wh + (long)(col0 + crow[i]) * IN_DIM + ckc[i] * 8;
    }

    float acc[4][4][4];
#pragma unroll
    for (int mt = 0; mt < 4; mt++)
#pragma unroll
        for (int nt = 0; nt < 4; nt++)
#pragma unroll
            for (int i = 0; i < 4; i++) acc[mt][nt][i] = 0.f;

    const int NKT = IN_DIM / GEMM_BK;   // 16

    auto issue_tile = [&](int s, int buf) {
        int koff = s * GEMM_BK;
#pragma unroll
        for (int i = 0; i < 2; i++) {
            unsigned off = buf * TILE_BYTES + crow[i] * (TILE_ROW_H * 2) + ckc[i] * 16;
            cp_async16(sA + off, aptr[i] + koff, avalid[i]);
            cp_async16(sB + off, bptr[i] + koff, 16);
        }
        cp_commit();
    };

    // per-lane ldmatrix base addresses (row-major tiles, k-contiguous)
    unsigned aaddr0 = sA + (wm + (lane & 15)) * (TILE_ROW_H * 2) + (lane >> 4) * 16;
    unsigned baddr0 = sB + (wn + (lane & 15)) * (TILE_ROW_H * 2) + (lane >> 4) * 16;

    // prologue: prefetch tiles 0..2 (stages-1)
    issue_tile(0, 0);
    issue_tile(1, 1);
    issue_tile(2, 2);

    for (int kt = 0; kt < NKT; kt++) {
        cp_wait2();               // <=2 groups pending -> tile kt resident
        __syncthreads();          // recycled buffer free across all warps

        if (kt + 3 < NKT) issue_tile(kt + 3, (kt + 3) % GEMM_STAGES);
        else              cp_commit();   // dummy group keeps wait_group 2 uniform

        unsigned stoff = (kt % GEMM_STAGES) * TILE_BYTES;
#pragma unroll
        for (int ks = 0; ks < 2; ks++) {          // two k16 steps per BK=32
            unsigned a[4][4], b[2][4];
#pragma unroll
            for (int mt = 0; mt < 4; mt++)
                ldsm_x4(a[mt], aaddr0 + stoff + mt * (16 * TILE_ROW_H * 2) + ks * 32);
#pragma unroll
            for (int np = 0; np < 2; np++)
                ldsm_x4(b[np], baddr0 + stoff + np * (16 * TILE_ROW_H * 2) + ks * 32);
#pragma unroll
            for (int mt = 0; mt < 4; mt++) {
                mma_fp16(acc[mt][0], a[mt], b[0][0], b[0][2]);
                mma_fp16(acc[mt][1], a[mt], b[0][1], b[0][3]);
                mma_fp16(acc[mt][2], a[mt], b[1][0], b[1][2]);
                mma_fp16(acc[mt][3], a[mt], b[1][1], b[1][3]);
            }
        }
    }

    // ---- epilogue: store feat as fp16 ----
#pragma unroll
    for (int mt = 0; mt < 4; mt++) {
#pragma unroll
        for (int nt = 0; nt < 4; nt++) {
            int row = row0 + wm + mt * 16 + fr;
            int col = col0 + wn + nt * 8 + 2 * fc;
            if (row < N_NODES)
                *(__half2*)&g_feath[(long)row * FEAT_DIM + col] =
                    __floats2half2_rn(acc[mt][nt][0], acc[mt][nt][1]);
            if (row + 8 < N_NODES)
                *(__half2*)&g_feath[(long)(row + 8) * FEAT_DIM + col] =
                    __floats2half2_rn(acc[mt][nt][2], acc[mt][nt][3]);
        }
    }

    // ---- epilogue: fused alpha partial dots ----
    {
        int head = (col0 + wn) >> 6;
        const float* a1 = att_w + head * (2 * OUT_DIM);
        const float* a2 = a1 + OUT_DIM;
        float s1[8], s2[8];
#pragma unroll
        for (int i = 0; i < 8; i++) { s1[i] = 0.f; s2[i] = 0.f; }
#pragma unroll
        for (int nt = 0; nt < 4; nt++) {
            int o = (wn & 63) + nt * 8 + 2 * fc;
            float w10 = a1[o], w11 = a1[o + 1];
            float w20 = a2[o], w21 = a2[o + 1];
#pragma unroll
            for (int mt = 0; mt < 4; mt++) {
                s1[mt*2]   = fmaf(acc[mt][nt][0], w10, fmaf(acc[mt][nt][1], w11, s1[mt*2]));
                s1[mt*2+1] = fmaf(acc[mt][nt][2], w10, fmaf(acc[mt][nt][3], w11, s1[mt*2+1]));
                s2[mt*2]   = fmaf(acc[mt][nt][0], w20, fmaf(acc[mt][nt][1], w21, s2[mt*2]));
                s2[mt*2+1] = fmaf(acc[mt][nt][2], w20, fmaf(acc[mt][nt][3], w21, s2[mt*2+1]));
            }
        }
#pragma unroll
        for (int i = 0; i < 8; i++) {
            s1[i] += __shfl_xor_sync(0xffffffffu, s1[i], 1);
            s1[i] += __shfl_xor_sync(0xffffffffu, s1[i], 2);
            s2[i] += __shfl_xor_sync(0xffffffffu, s2[i], 1);
            s2[i] += __shfl_xor_sync(0xffffffffu, s2[i], 2);
        }
        if (fc == 0) {
#pragma unroll
            for (int i = 0; i < 8; i++) {
                int row = row0 + wm + (i >> 1) * 16 + fr + (i & 1) * 8;
                if (row < N_NODES) {
                    atomicAdd(&g_alpha_s[row * N_HEADS + head], s1[i]);
                    atomicAdd(&g_alpha_d[row * N_HEADS + head], s2[i]);
                }
            }
        }
    }
}

// ---------------- CSR construction -------------------------------------------
__global__ void count_kernel(const int* __restrict__ src) {
    int e = blockIdx.x * blockDim.x + threadIdx.x;
    if (e < N_EDGES) atomicAdd(&g_deg[src[e]], 1);
}

// 3-phase scan: block-local scan -> scan of block sums -> add offsets
__global__ __launch_bounds__(1024) void scan1_kernel() {
    __shared__ int wsum[32];
    int tid = threadIdx.x, b = blockIdx.x;
    int i = b * 1024 + tid;
    int lane = tid & 31, wp = tid >> 5;
    int v = (i < N_NODES) ? g_deg[i] : 0;
    int x = v;
#pragma unroll
    for (int off = 1; off < 32; off <<= 1) {
        int y = __shfl_up_sync(0xffffffffu, x, off);
        if (lane >= off) x += y;
    }
    if (lane == 31) wsum[wp] = x;
    __syncthreads();
    if (wp == 0) {
        int s = wsum[lane];
#pragma unroll
        for (int off = 1; off < 32; off <<= 1) {
            int y = __shfl_up_sync(0xffffffffu, s, off);
            if (lane >= off) s += y;
        }
        wsum[lane] = s;
    }
    __syncthreads();
    int incl = x + (wp ? wsum[wp - 1] : 0);
    if (i < N_NODES) g_rowstart[i] = incl - v;   // block-local exclusive
    if (tid == 1023) g_bsum[b] = incl;
}

__global__ void scan2_kernel() {   // 1 block, 64 threads, SCAN_NB=49 sums
    __shared__ int t0;
    int tid = threadIdx.x, lane = tid & 31, wp = tid >> 5;
    int v = (tid < SCAN_NB) ? g_bsum[tid] : 0;
    int x = v;
#pragma unroll
    for (int off = 1; off < 32; off <<= 1) {
        int y = __shfl_up_sync(0xffffffffu, x, off);
        if (lane >= off) x += y;
    }
    if (wp == 0 && lane == 31) t0 = x;
    __syncthreads();
    int incl = x + (wp ? t0 : 0);
    if (tid < SCAN_NB) g_boff[tid] = incl - v;
    if (tid == SCAN_NB - 1) g_rowstart[N_NODES] = incl;
}

__global__ __launch_bounds__(1024) void scan3_kernel() {
    int i = blockIdx.x * 1024 + threadIdx.x;
    if (i < N_NODES) g_rowstart[i] += g_boff[blockIdx.x];
}

__global__ void fill_kernel(const int* __restrict__ src, const int* __restrict__ dst) {
    int e = blockIdx.x * blockDim.x + threadIdx.x;
    if (e < N_EDGES) {
        int s = src[e];
        int p = atomicAdd(&g_cursor[s], 1);
        g_csr_dst[g_rowstart[s] + p] = dst[e];
    }
}

// ---------------- per-node softmax + aggregation (fp16 gather) ---------------
// one block (256 threads = 8 warps) per src node
__global__ __launch_bounds__(256) void agg_kernel(float* __restrict__ out) {
    int n   = blockIdx.x;
    int tid = threadIdx.x;
    int rs  = g_rowstart[n];
    int deg = g_rowstart[n + 1] - rs;

    __shared__ float s_as[N_HEADS];
    __shared__ float s_inv[N_HEADS];
    __shared__ int   s_d[32];
    __shared__ float s_att[32 * N_HEADS];

    // ---- phase A: per-head exp-sum (warp w = head w); logits are O(±6), safe
    int w = tid >> 5, l = tid & 31;
    float as = g_alpha_s[n * N_HEADS + w];
    float s = 0.f;
    for (int e = l; e < deg; e += 32) {
        int d = g_csr_dst[rs + e];
        float v = as + g_alpha_d[d * N_HEADS + w];
        v = (v > 0.f) ? v : LRELU_ALPHA * v;
        s += __expf(v);
    }
#pragma unroll
    for (int o = 16; o; o >>= 1) s += __shfl_xor_sync(0xffffffffu, s, o);
    if (l == 0) {
        s_as[w]  = as;
        s_inv[w] = (deg > 0) ? (1.0f / s) : 0.f;
    }
    __syncthreads();

    // ---- phase B: weighted gather-accumulate (half2, 4B/thread/edge) ----
    float2 acc = make_float2(0.f, 0.f);
    const __half2* fh = (const __half2*)g_feath;
    int hh = tid >> 5;                    // head for columns [tid*2, tid*2+1]

    for (int c = 0; c < deg; c += 32) {
        int len = min(32, deg - c);
        __syncthreads();                  // protect s_d/s_att reuse
        if (tid < len) s_d[tid] = g_csr_dst[rs + c + tid];
        __syncthreads();
        {
            int i = tid >> 3, h = tid & 7;
            if (i < len) {
                int d = s_d[i];
                float v = s_as[h] + g_alpha_d[d * N_HEADS + h];
                v = (v > 0.f) ? v : LRELU_ALPHA * v;
                s_att[i * 8 + h] = __expf(v) * s_inv[h];
            }
        }
        __syncthreads();
        for (int i = 0; i < len; i++) {
            int d = s_d[i];
            float a = s_att[i * 8 + hh];
            float2 f = __half22float2(fh[(long)d * (FEAT_DIM / 2) + tid]);
            acc.x = fmaf(a, f.x, acc.x);
            acc.y = fmaf(a, f.y, acc.y);
        }
    }

    float2* o2 = (float2*)out;
    o2[(long)n * (FEAT_DIM / 2) + tid] =
        make_float2(fmaxf(acc.x, 0.f), fmaxf(acc.y, 0.f));
}

// ---------------- launch ------------------------------------------------------
extern "C" void kernel_launch(void* const* d_in, const int* in_sizes, int n_in,
                              void* d_out, int out_size) {
    const float* x     = (const float*)d_in[0];
    const float* W     = (const float*)d_in[1];
    const float* att_w = (const float*)d_in[2];
    const int*   src   = (const int*)d_in[3];
    const int*   dst   = (const int*)d_in[4];
    float* out = (float*)d_out;

    cudaFuncSetAttribute(gemm_fp16_kernel,
                         cudaFuncAttributeMaxDynamicSharedMemorySize, GEMM_SMEM_BYTES);

    prep_kernel<<<1024, 256>>>(x, W);          // zero + conv_x + conv_w fused
    count_kernel<<<(N_EDGES + 255) / 256, 256>>>(src);
    scan1_kernel<<<SCAN_NB, 1024>>>();
    gemm_fp16_kernel<<<dim3(FEAT_DIM / GEMM_BN, (N_NODES + GEMM_BM - 1) / GEMM_BM),
                      256, GEMM_SMEM_BYTES>>>(att_w);   // 4th launch: ncu target
    scan2_kernel<<<1, 64>>>();
    scan3_kernel<<<SCAN_NB, 1024>>>();
    fill_kernel<<<(N_EDGES + 255) / 256, 256>>>(src, dst);
    agg_kernel<<<N_NODES, 256>>>(out);
}

// round 12
// speedup vs baseline: 1.0687x; 1.0341x over previous
#include <cuda_runtime.h>
#include <cuda_fp16.h>
#include <math.h>

#define N_NODES 50000
#define N_EDGES 1600000
#define N_HEADS 8
#define IN_DIM  512
#define OUT_DIM 64
#define FEAT_DIM 512   // N_HEADS * OUT_DIM
#define LRELU_ALPHA 0.2f
#define SCAN_NB 49     // ceil(50000 / 1024)

// ---------------- scratch (device globals; no allocation allowed) -----------
__device__ __half g_xh[N_NODES * IN_DIM];        // 51.2 MB fp16 copy of x
__device__ __half g_wh[FEAT_DIM * IN_DIM];       // 0.5 MB  B^T[j][k] fp16
__device__ __half g_feath[N_NODES * FEAT_DIM];   // 51.2 MB (gather source, fp16)
__device__ float g_alpha_s[N_NODES * N_HEADS];
__device__ float g_alpha_d[N_NODES * N_HEADS];
__device__ int   g_deg[N_NODES];
__device__ int   g_cursor[N_NODES];
__device__ int   g_rowstart[N_NODES + 1];
__device__ int   g_csr_dst[N_EDGES];
__device__ int   g_bsum[64];
__device__ int   g_boff[64];

// ---------------- fused prep: zero counters/alpha + x->fp16 + W->B^T fp16 ----
__global__ __launch_bounds__(256) void prep_kernel(const float* __restrict__ x,
                                                   const float* __restrict__ W) {
    int i = blockIdx.x * blockDim.x + threadIdx.x;
    int stride = gridDim.x * blockDim.x;
    for (int j = i; j < N_NODES * N_HEADS; j += stride) {
        g_alpha_s[j] = 0.f;
        g_alpha_d[j] = 0.f;
    }
    for (int j = i; j < N_NODES; j += stride) {
        g_deg[j] = 0;
        g_cursor[j] = 0;
    }
    const int n4 = N_NODES * IN_DIM / 4;
    for (int j = i; j < n4; j += stride) {
        float4 v = *(const float4*)(x + j * 4);
        __half2* o = (__half2*)(g_xh + j * 4);
        o[0] = __floats2half2_rn(v.x, v.y);
        o[1] = __floats2half2_rn(v.z, v.w);
    }
    for (int p = i; p < FEAT_DIM * IN_DIM; p += stride) {
        int j = p >> 9, k = p & 511;
        int h = j >> 6, o = j & 63;
        g_wh[j * IN_DIM + k] = __float2half_rn(W[((long)h * IN_DIM + k) * OUT_DIM + o]);
    }
}

// ---------------- fp16 tensor-core GEMM: feat = x @ W (+ fused alpha) --------
// A = g_xh [node][k], B^T = g_wh [j][k]; mma.m16n8k16 via ldmatrix.
// BM=128, BN=128, BK=32; 8 warps x (64x32); 4-stage cp.async pipeline.
#define GEMM_BM 128
#define GEMM_BN 128
#define GEMM_BK 32
#define GEMM_STAGES 4
#define TILE_ROW_H 40                          // halves per smem row (80 B)
#define TILE_BYTES (128 * TILE_ROW_H * 2)      // 10240 per tile
#define GEMM_SMEM_BYTES (GEMM_STAGES * 2 * TILE_BYTES)   // 81920

__device__ __forceinline__ void ldsm_x4(unsigned* r, unsigned addr) {
    asm volatile("ldmatrix.sync.aligned.m8n8.x4.shared.b16 {%0,%1,%2,%3}, [%4];"
                 : "=r"(r[0]), "=r"(r[1]), "=r"(r[2]), "=r"(r[3]) : "r"(addr));
}

__device__ __forceinline__ void mma_fp16(float* c, const unsigned* a,
                                         unsigned b0, unsigned b1) {
    asm volatile(
        "mma.sync.aligned.m16n8k16.row.col.f32.f16.f16.f32 "
        "{%0,%1,%2,%3},{%4,%5,%6,%7},{%8,%9},{%0,%1,%2,%3};"
        : "+f"(c[0]), "+f"(c[1]), "+f"(c[2]), "+f"(c[3])
        : "r"(a[0]), "r"(a[1]), "r"(a[2]), "r"(a[3]), "r"(b0), "r"(b1));
}

__device__ __forceinline__ void cp_async16(unsigned saddr, const void* g, int srcbytes) {
    asm volatile("cp.async.cg.shared.global [%0], [%1], 16, %2;\n"
                 :: "r"(saddr), "l"(g), "r"(srcbytes));
}
__device__ __forceinline__ void cp_commit() {
    asm volatile("cp.async.commit_group;\n");
}
__device__ __forceinline__ void cp_wait2() {
    asm volatile("cp.async.wait_group 2;\n");
}

__global__ __launch_bounds__(256) void gemm_fp16_kernel(const float* __restrict__ att_w) {
    extern __shared__ __half hsm[];
    unsigned sA = (unsigned)__cvta_generic_to_shared(hsm);
    unsigned sB = sA + GEMM_STAGES * TILE_BYTES;

    const int t    = threadIdx.x;
    const int lane = t & 31;
    const int wid  = t >> 5;
    const int row0 = blockIdx.y * GEMM_BM;
    const int col0 = blockIdx.x * GEMM_BN;

    const int wm = (wid & 1) * 64;
    const int wn = (wid >> 1) * 32;
    const int fr = lane >> 2;   // 0..7
    const int fc = lane & 3;    // 0..3

    int crow[2], ckc[2], avalid[2];
    const __half* aptr[2];
    const __half* bptr[2];
#pragma unroll
    for (int i = 0; i < 2; i++) {
        int chunk = t + 256 * i;       // 0..511
        crow[i] = chunk >> 2;          // 0..127
        ckc[i]  = chunk & 3;           // 16B chunk within 64B row
        int gr  = row0 + crow[i];
        avalid[i] = (gr < N_NODES) ? 16 : 0;
        aptr[i] = g_xh + (long)gr * IN_DIM + ckc[i] * 8;
        bptr[i] = g_wh + (long)(col0 + crow[i]) * IN_DIM + ckc[i] * 8;
    }

    float acc[4][4][4];
#pragma unroll
    for (int mt = 0; mt < 4; mt++)
#pragma unroll
        for (int nt = 0; nt < 4; nt++)
#pragma unroll
            for (int i = 0; i < 4; i++) acc[mt][nt][i] = 0.f;

    const int NKT = IN_DIM / GEMM_BK;   // 16

    auto issue_tile = [&](int s, int buf) {
        int koff = s * GEMM_BK;
#pragma unroll
        for (int i = 0; i < 2; i++) {
            unsigned off = buf * TILE_BYTES + crow[i] * (TILE_ROW_H * 2) + ckc[i] * 16;
            cp_async16(sA + off, aptr[i] + koff, avalid[i]);
            cp_async16(sB + off, bptr[i] + koff, 16);
        }
        cp_commit();
    };

    unsigned aaddr0 = sA + (wm + (lane & 15)) * (TILE_ROW_H * 2) + (lane >> 4) * 16;
    unsigned baddr0 = sB + (wn + (lane & 15)) * (TILE_ROW_H * 2) + (lane >> 4) * 16;

    issue_tile(0, 0);
    issue_tile(1, 1);
    issue_tile(2, 2);

    for (int kt = 0; kt < NKT; kt++) {
        cp_wait2();
        __syncthreads();

        if (kt + 3 < NKT) issue_tile(kt + 3, (kt + 3) % GEMM_STAGES);
        else              cp_commit();

        unsigned stoff = (kt % GEMM_STAGES) * TILE_BYTES;
#pragma unroll
        for (int ks = 0; ks < 2; ks++) {
            unsigned a[4][4], b[2][4];
#pragma unroll
            for (int mt = 0; mt < 4; mt++)
                ldsm_x4(a[mt], aaddr0 + stoff + mt * (16 * TILE_ROW_H * 2) + ks * 32);
#pragma unroll
            for (int np = 0; np < 2; np++)
                ldsm_x4(b[np], baddr0 + stoff + np * (16 * TILE_ROW_H * 2) + ks * 32);
#pragma unroll
            for (int mt = 0; mt < 4; mt++) {
                mma_fp16(acc[mt][0], a[mt], b[0][0], b[0][2]);
                mma_fp16(acc[mt][1], a[mt], b[0][1], b[0][3]);
                mma_fp16(acc[mt][2], a[mt], b[1][0], b[1][2]);
                mma_fp16(acc[mt][3], a[mt], b[1][1], b[1][3]);
            }
        }
    }

    // ---- epilogue: store feat as fp16 ----
#pragma unroll
    for (int mt = 0; mt < 4; mt++) {
#pragma unroll
        for (int nt = 0; nt < 4; nt++) {
            int row = row0 + wm + mt * 16 + fr;
            int col = col0 + wn + nt * 8 + 2 * fc;
            if (row < N_NODES)
                *(__half2*)&g_feath[(long)row * FEAT_DIM + col] =
                    __floats2half2_rn(acc[mt][nt][0], acc[mt][nt][1]);
            if (row + 8 < N_NODES)
                *(__half2*)&g_feath[(long)(row + 8) * FEAT_DIM + col] =
                    __floats2half2_rn(acc[mt][nt][2], acc[mt][nt][3]);
        }
    }

    // ---- epilogue: fused alpha partial dots ----
    {
        int head = (col0 + wn) >> 6;
        const float* a1 = att_w + head * (2 * OUT_DIM);
        const float* a2 = a1 + OUT_DIM;
        float s1[8], s2[8];
#pragma unroll
        for (int i = 0; i < 8; i++) { s1[i] = 0.f; s2[i] = 0.f; }
#pragma unroll
        for (int nt = 0; nt < 4; nt++) {
            int o = (wn & 63) + nt * 8 + 2 * fc;
            float w10 = a1[o], w11 = a1[o + 1];
            float w20 = a2[o], w21 = a2[o + 1];
#pragma unroll
            for (int mt = 0; mt < 4; mt++) {
                s1[mt*2]   = fmaf(acc[mt][nt][0], w10, fmaf(acc[mt][nt][1], w11, s1[mt*2]));
                s1[mt*2+1] = fmaf(acc[mt][nt][2], w10, fmaf(acc[mt][nt][3], w11, s1[mt*2+1]));
                s2[mt*2]   = fmaf(acc[mt][nt][0], w20, fmaf(acc[mt][nt][1], w21, s2[mt*2]));
                s2[mt*2+1] = fmaf(acc[mt][nt][2], w20, fmaf(acc[mt][nt][3], w21, s2[mt*2+1]));
            }
        }
#pragma unroll
        for (int i = 0; i < 8; i++) {
            s1[i] += __shfl_xor_sync(0xffffffffu, s1[i], 1);
            s1[i] += __shfl_xor_sync(0xffffffffu, s1[i], 2);
            s2[i] += __shfl_xor_sync(0xffffffffu, s2[i], 1);
            s2[i] += __shfl_xor_sync(0xffffffffu, s2[i], 2);
        }
        if (fc == 0) {
#pragma unroll
            for (int i = 0; i < 8; i++) {
                int row = row0 + wm + (i >> 1) * 16 + fr + (i & 1) * 8;
                if (row < N_NODES) {
                    atomicAdd(&g_alpha_s[row * N_HEADS + head], s1[i]);
                    atomicAdd(&g_alpha_d[row * N_HEADS + head], s2[i]);
                }
            }
        }
    }
}

// ---------------- CSR construction -------------------------------------------
__global__ void count_kernel(const int* __restrict__ src) {
    int e = blockIdx.x * blockDim.x + threadIdx.x;
    if (e < N_EDGES) atomicAdd(&g_deg[src[e]], 1);
}

__global__ __launch_bounds__(1024) void scan1_kernel() {
    __shared__ int wsum[32];
    int tid = threadIdx.x, b = blockIdx.x;
    int i = b * 1024 + tid;
    int lane = tid & 31, wp = tid >> 5;
    int v = (i < N_NODES) ? g_deg[i] : 0;
    int x = v;
#pragma unroll
    for (int off = 1; off < 32; off <<= 1) {
        int y = __shfl_up_sync(0xffffffffu, x, off);
        if (lane >= off) x += y;
    }
    if (lane == 31) wsum[wp] = x;
    __syncthreads();
    if (wp == 0) {
        int s = wsum[lane];
#pragma unroll
        for (int off = 1; off < 32; off <<= 1) {
            int y = __shfl_up_sync(0xffffffffu, s, off);
            if (lane >= off) s += y;
        }
        wsum[lane] = s;
    }
    __syncthreads();
    int incl = x + (wp ? wsum[wp - 1] : 0);
    if (i < N_NODES) g_rowstart[i] = incl - v;
    if (tid == 1023) g_bsum[b] = incl;
}

__global__ void scan2_kernel() {
    __shared__ int t0;
    int tid = threadIdx.x, lane = tid & 31, wp = tid >> 5;
    int v = (tid < SCAN_NB) ? g_bsum[tid] : 0;
    int x = v;
#pragma unroll
    for (int off = 1; off < 32; off <<= 1) {
        int y = __shfl_up_sync(0xffffffffu, x, off);
        if (lane >= off) x += y;
    }
    if (wp == 0 && lane == 31) t0 = x;
    __syncthreads();
    int incl = x + (wp ? t0 : 0);
    if (tid < SCAN_NB) g_boff[tid] = incl - v;
    if (tid == SCAN_NB - 1) g_rowstart[N_NODES] = incl;
}

__global__ __launch_bounds__(1024) void scan3_kernel() {
    int i = blockIdx.x * 1024 + threadIdx.x;
    if (i < N_NODES) g_rowstart[i] += g_boff[blockIdx.x];
}

__global__ void fill_kernel(const int* __restrict__ src, const int* __restrict__ dst) {
    int e = blockIdx.x * blockDim.x + threadIdx.x;
    if (e < N_EDGES) {
        int s = src[e];
        int p = atomicAdd(&g_cursor[s], 1);
        g_csr_dst[g_rowstart[s] + p] = dst[e];
    }
}

// ---------------- single-pass softmax + aggregation (fp16 gather) ------------
// one block (256 threads = 8 warps) per src node.
// Accumulate UNNORMALIZED sum(e * feat) and sum(e); scale by 1/sum(e) at end.
__global__ __launch_bounds__(256) void agg_kernel(float* __restrict__ out) {
    int n   = blockIdx.x;
    int tid = threadIdx.x;
    int rs  = g_rowstart[n];
    int deg = g_rowstart[n + 1] - rs;

    __shared__ float s_as[N_HEADS];
    __shared__ float s_inv[N_HEADS];
    __shared__ int   s_d[32];
    __shared__ float s_att[32 * N_HEADS];
    __shared__ float s_part[8][9];

    int w  = tid >> 5, l = tid & 31;
    int ii = tid >> 3, h = tid & 7;       // edge-slot, head (coalesced alpha_d)
    int hh = tid >> 5;                    // head for output cols [tid*2, tid*2+1]

    if (tid < N_HEADS) s_as[tid] = g_alpha_s[n * N_HEADS + tid];
    __syncthreads();
    float as_h = s_as[h];

    float2 acc = make_float2(0.f, 0.f);
    float esum = 0.f;
    const __half2* fh = (const __half2*)g_feath;

    for (int c = 0; c < deg; c += 32) {
        int len = min(32, deg - c);
        __syncthreads();                  // prior chunk's s_d/s_att fully consumed
        if (tid < len) s_d[tid] = g_csr_dst[rs + c + tid];
        __syncthreads();
        if (ii < len) {
            int d = s_d[ii];
            // 8 threads share d -> one coalesced 32B sector per edge
            float v = as_h + g_alpha_d[d * N_HEADS + h];
            v = (v > 0.f) ? v : LRELU_ALPHA * v;
            float e = __expf(v);
            s_att[ii * 8 + h] = e;        // unnormalized
            esum += e;
        }
        __syncthreads();
        for (int i = 0; i < len; i++) {
            int d = s_d[i];
            float a = s_att[i * 8 + hh];
            float2 f = __half22float2(fh[(long)d * (FEAT_DIM / 2) + tid]);
            acc.x = fmaf(a, f.x, acc.x);
            acc.y = fmaf(a, f.y, acc.y);
        }
    }

    // reduce esum over threads sharing the same head: lanes l, l^8, l^16
    esum += __shfl_xor_sync(0xffffffffu, esum, 8);
    esum += __shfl_xor_sync(0xffffffffu, esum, 16);
    if (l < 8) s_part[w][l] = esum;
    __syncthreads();
    if (tid < N_HEADS) {
        float s = 0.f;
#pragma unroll
        for (int ww = 0; ww < 8; ww++) s += s_part[ww][tid];
        s_inv[tid] = (deg > 0) ? (1.0f / s) : 0.f;
    }
    __syncthreads();

    float inv = s_inv[hh];
    float2* o2 = (float2*)out;
    o2[(long)n * (FEAT_DIM / 2) + tid] =
        make_float2(fmaxf(acc.x * inv, 0.f), fmaxf(acc.y * inv, 0.f));
}

// ---------------- launch ------------------------------------------------------
extern "C" void kernel_launch(void* const* d_in, const int* in_sizes, int n_in,
                              void* d_out, int out_size) {
    const float* x     = (const float*)d_in[0];
    const float* W     = (const float*)d_in[1];
    const float* att_w = (const float*)d_in[2];
    const int*   src   = (const int*)d_in[3];
    const int*   dst   = (const int*)d_in[4];
    float* out = (float*)d_out;

    cudaFuncSetAttribute(gemm_fp16_kernel,
                         cudaFuncAttributeMaxDynamicSharedMemorySize, GEMM_SMEM_BYTES);

    prep_kernel<<<1024, 256>>>(x, W);
    count_kernel<<<(N_EDGES + 255) / 256, 256>>>(src);
    scan1_kernel<<<SCAN_NB, 1024>>>();
    gemm_fp16_kernel<<<dim3(FEAT_DIM / GEMM_BN, (N_NODES + GEMM_BM - 1) / GEMM_BM),
                      256, GEMM_SMEM_BYTES>>>(att_w);   // 4th launch: ncu target
    scan2_kernel<<<1, 64>>>();
    scan3_kernel<<<SCAN_NB, 1024>>>();
    fill_kernel<<<(N_EDGES + 255) / 256, 256>>>(src, dst);
    agg_kernel<<<N_NODES, 256>>>(out);
}

// round 13
// speedup vs baseline: 1.1103x; 1.0389x over previous
#include <cuda_runtime.h>
#include <cuda_fp16.h>
#include <math.h>

#define N_NODES 50000
#define N_EDGES 1600000
#define N_HEADS 8
#define IN_DIM  512
#define OUT_DIM 64
#define FEAT_DIM 512   // N_HEADS * OUT_DIM
#define LRELU_ALPHA 0.2f
#define SCAN_NB 49     // ceil(50000 / 1024)

// ---------------- scratch (device globals; no allocation allowed) -----------
__device__ __half g_xh[N_NODES * IN_DIM];        // 51.2 MB fp16 copy of x
__device__ __half g_wh[FEAT_DIM * IN_DIM];       // 0.5 MB  B^T[j][k] fp16
__device__ __half g_feath[N_NODES * FEAT_DIM];   // 51.2 MB (gather source, fp16)
__device__ float g_alpha_s[N_NODES * N_HEADS];
__device__ float g_alpha_d[N_NODES * N_HEADS];
__device__ int   g_deg[N_NODES];
__device__ int   g_cursor[N_NODES];
__device__ int   g_rowstart[N_NODES + 1];
__device__ int   g_csr_dst[N_EDGES];
__device__ int   g_bsum[64];
__device__ int   g_boff[64];

// ---------------- prep (branch A): zero alpha + x->fp16 + W->B^T fp16 --------
__global__ __launch_bounds__(256) void prep_kernel(const float* __restrict__ x,
                                                   const float* __restrict__ W) {
    int i = blockIdx.x * blockDim.x + threadIdx.x;
    int stride = gridDim.x * blockDim.x;
    for (int j = i; j < N_NODES * N_HEADS; j += stride) {
        g_alpha_s[j] = 0.f;
        g_alpha_d[j] = 0.f;
    }
    const int n4 = N_NODES * IN_DIM / 4;
    for (int j = i; j < n4; j += stride) {
        float4 v = *(const float4*)(x + j * 4);
        __half2* o = (__half2*)(g_xh + j * 4);
        o[0] = __floats2half2_rn(v.x, v.y);
        o[1] = __floats2half2_rn(v.z, v.w);
    }
    for (int p = i; p < FEAT_DIM * IN_DIM; p += stride) {
        int j = p >> 9, k = p & 511;
        int h = j >> 6, o = j & 63;
        g_wh[j * IN_DIM + k] = __float2half_rn(W[((long)h * IN_DIM + k) * OUT_DIM + o]);
    }
}

// ---------------- zero (branch B): deg + cursor -------------------------------
__global__ void zero_csr_kernel() {
    int i = blockIdx.x * blockDim.x + threadIdx.x;
    int stride = gridDim.x * blockDim.x;
    for (int j = i; j < N_NODES; j += stride) {
        g_deg[j] = 0;
        g_cursor[j] = 0;
    }
}

// ---------------- fp16 tensor-core GEMM: feat = x @ W (+ fused alpha) --------
// A = g_xh [node][k], B^T = g_wh [j][k]; mma.m16n8k16 via ldmatrix.
// BM=128, BN=128, BK=32; 8 warps x (64x32); 4-stage cp.async pipeline.
#define GEMM_BM 128
#define GEMM_BN 128
#define GEMM_BK 32
#define GEMM_STAGES 4
#define TILE_ROW_H 40                          // halves per smem row (80 B)
#define TILE_BYTES (128 * TILE_ROW_H * 2)      // 10240 per tile
#define GEMM_SMEM_BYTES (GEMM_STAGES * 2 * TILE_BYTES)   // 81920

__device__ __forceinline__ void ldsm_x4(unsigned* r, unsigned addr) {
    asm volatile("ldmatrix.sync.aligned.m8n8.x4.shared.b16 {%0,%1,%2,%3}, [%4];"
                 : "=r"(r[0]), "=r"(r[1]), "=r"(r[2]), "=r"(r[3]) : "r"(addr));
}

__device__ __forceinline__ void mma_fp16(float* c, const unsigned* a,
                                         unsigned b0, unsigned b1) {
    asm volatile(
        "mma.sync.aligned.m16n8k16.row.col.f32.f16.f16.f32 "
        "{%0,%1,%2,%3},{%4,%5,%6,%7},{%8,%9},{%0,%1,%2,%3};"
        : "+f"(c[0]), "+f"(c[1]), "+f"(c[2]), "+f"(c[3])
        : "r"(a[0]), "r"(a[1]), "r"(a[2]), "r"(a[3]), "r"(b0), "r"(b1));
}

__device__ __forceinline__ void cp_async16(unsigned saddr, const void* g, int srcbytes) {
    asm volatile("cp.async.cg.shared.global [%0], [%1], 16, %2;\n"
                 :: "r"(saddr), "l"(g), "r"(srcbytes));
}
__device__ __forceinline__ void cp_commit() {
    asm volatile("cp.async.commit_group;\n");
}
__device__ __forceinline__ void cp_wait2() {
    asm volatile("cp.async.wait_group 2;\n");
}

__global__ __launch_bounds__(256) void gemm_fp16_kernel(const float* __restrict__ att_w) {
    extern __shared__ __half hsm[];
    unsigned sA = (unsigned)__cvta_generic_to_shared(hsm);
    unsigned sB = sA + GEMM_STAGES * TILE_BYTES;

    const int t    = threadIdx.x;
    const int lane = t & 31;
    const int wid  = t >> 5;
    const int row0 = blockIdx.y * GEMM_BM;
    const int col0 = blockIdx.x * GEMM_BN;

    const int wm = (wid & 1) * 64;
    const int wn = (wid >> 1) * 32;
    const int fr = lane >> 2;   // 0..7
    const int fc = lane & 3;    // 0..3

    int crow[2], ckc[2], avalid[2];
    const __half* aptr[2];
    const __half* bptr[2];
#pragma unroll
    for (int i = 0; i < 2; i++) {
        int chunk = t + 256 * i;       // 0..511
        crow[i] = chunk >> 2;          // 0..127
        ckc[i]  = chunk & 3;           // 16B chunk within 64B row
        int gr  = row0 + crow[i];
        avalid[i] = (gr < N_NODES) ? 16 : 0;
        aptr[i] = g_xh + (long)gr * IN_DIM + ckc[i] * 8;
        bptr[i] = g_wh + (long)(col0 + crow[i]) * IN_DIM + ckc[i] * 8;
    }

    float acc[4][4][4];
#pragma unroll
    for (int mt = 0; mt < 4; mt++)
#pragma unroll
        for (int nt = 0; nt < 4; nt++)
#pragma unroll
            for (int i = 0; i < 4; i++) acc[mt][nt][i] = 0.f;

    const int NKT = IN_DIM / GEMM_BK;   // 16

    auto issue_tile = [&](int s, int buf) {
        int koff = s * GEMM_BK;
#pragma unroll
        for (int i = 0; i < 2; i++) {
            unsigned off = buf * TILE_BYTES + crow[i] * (TILE_ROW_H * 2) + ckc[i] * 16;
            cp_async16(sA + off, aptr[i] + koff, avalid[i]);
            cp_async16(sB + off, bptr[i] + koff, 16);
        }
        cp_commit();
    };

    unsigned aaddr0 = sA + (wm + (lane & 15)) * (TILE_ROW_H * 2) + (lane >> 4) * 16;
    unsigned baddr0 = sB + (wn + (lane & 15)) * (TILE_ROW_H * 2) + (lane >> 4) * 16;

    issue_tile(0, 0);
    issue_tile(1, 1);
    issue_tile(2, 2);

    for (int kt = 0; kt < NKT; kt++) {
        cp_wait2();
        __syncthreads();

        if (kt + 3 < NKT) issue_tile(kt + 3, (kt + 3) % GEMM_STAGES);
        else              cp_commit();

        unsigned stoff = (kt % GEMM_STAGES) * TILE_BYTES;
#pragma unroll
        for (int ks = 0; ks < 2; ks++) {
            unsigned a[4][4], b[2][4];
#pragma unroll
            for (int mt = 0; mt < 4; mt++)
                ldsm_x4(a[mt], aaddr0 + stoff + mt * (16 * TILE_ROW_H * 2) + ks * 32);
#pragma unroll
            for (int np = 0; np < 2; np++)
                ldsm_x4(b[np], baddr0 + stoff + np * (16 * TILE_ROW_H * 2) + ks * 32);
#pragma unroll
            for (int mt = 0; mt < 4; mt++) {
                mma_fp16(acc[mt][0], a[mt], b[0][0], b[0][2]);
                mma_fp16(acc[mt][1], a[mt], b[0][1], b[0][3]);
                mma_fp16(acc[mt][2], a[mt], b[1][0], b[1][2]);
                mma_fp16(acc[mt][3], a[mt], b[1][1], b[1][3]);
            }
        }
    }

    // ---- epilogue: store feat as fp16 ----
#pragma unroll
    for (int mt = 0; mt < 4; mt++) {
#pragma unroll
        for (int nt = 0; nt < 4; nt++) {
            int row = row0 + wm + mt * 16 + fr;
            int col = col0 + wn + nt * 8 + 2 * fc;
            if (row < N_NODES)
                *(__half2*)&g_feath[(long)row * FEAT_DIM + col] =
                    __floats2half2_rn(acc[mt][nt][0], acc[mt][nt][1]);
            if (row + 8 < N_NODES)
                *(__half2*)&g_feath[(long)(row + 8) * FEAT_DIM + col] =
                    __floats2half2_rn(acc[mt][nt][2], acc[mt][nt][3]);
        }
    }

    // ---- epilogue: fused alpha partial dots ----
    {
        int head = (col0 + wn) >> 6;
        const float* a1 = att_w + head * (2 * OUT_DIM);
        const float* a2 = a1 + OUT_DIM;
        float s1[8], s2[8];
#pragma unroll
        for (int i = 0; i < 8; i++) { s1[i] = 0.f; s2[i] = 0.f; }
#pragma unroll
        for (int nt = 0; nt < 4; nt++) {
            int o = (wn & 63) + nt * 8 + 2 * fc;
            float w10 = a1[o], w11 = a1[o + 1];
            float w20 = a2[o], w21 = a2[o + 1];
#pragma unroll
            for (int mt = 0; mt < 4; mt++) {
                s1[mt*2]   = fmaf(acc[mt][nt][0], w10, fmaf(acc[mt][nt][1], w11, s1[mt*2]));
                s1[mt*2+1] = fmaf(acc[mt][nt][2], w10, fmaf(acc[mt][nt][3], w11, s1[mt*2+1]));
                s2[mt*2]   = fmaf(acc[mt][nt][0], w20, fmaf(acc[mt][nt][1], w21, s2[mt*2]));
                s2[mt*2+1] = fmaf(acc[mt][nt][2], w20, fmaf(acc[mt][nt][3], w21, s2[mt*2+1]));
            }
        }
#pragma unroll
        for (int i = 0; i < 8; i++) {
            s1[i] += __shfl_xor_sync(0xffffffffu, s1[i], 1);
            s1[i] += __shfl_xor_sync(0xffffffffu, s1[i], 2);
            s2[i] += __shfl_xor_sync(0xffffffffu, s2[i], 1);
            s2[i] += __shfl_xor_sync(0xffffffffu, s2[i], 2);
        }
        if (fc == 0) {
#pragma unroll
            for (int i = 0; i < 8; i++) {
                int row = row0 + wm + (i >> 1) * 16 + fr + (i & 1) * 8;
                if (row < N_NODES) {
                    atomicAdd(&g_alpha_s[row * N_HEADS + head], s1[i]);
                    atomicAdd(&g_alpha_d[row * N_HEADS + head], s2[i]);
                }
            }
        }
    }
}

// ---------------- CSR construction -------------------------------------------
__global__ void count_kernel(const int* __restrict__ src) {
    int e = blockIdx.x * blockDim.x + threadIdx.x;
    if (e < N_EDGES) atomicAdd(&g_deg[src[e]], 1);
}

__global__ __launch_bounds__(1024) void scan1_kernel() {
    __shared__ int wsum[32];
    int tid = threadIdx.x, b = blockIdx.x;
    int i = b * 1024 + tid;
    int lane = tid & 31, wp = tid >> 5;
    int v = (i < N_NODES) ? g_deg[i] : 0;
    int x = v;
#pragma unroll
    for (int off = 1; off < 32; off <<= 1) {
        int y = __shfl_up_sync(0xffffffffu, x, off);
        if (lane >= off) x += y;
    }
    if (lane == 31) wsum[wp] = x;
    __syncthreads();
    if (wp == 0) {
        int s = wsum[lane];
#pragma unroll
        for (int off = 1; off < 32; off <<= 1) {
            int y = __shfl_up_sync(0xffffffffu, s, off);
            if (lane >= off) s += y;
        }
        wsum[lane] = s;
    }
    __syncthreads();
    int incl = x + (wp ? wsum[wp - 1] : 0);
    if (i < N_NODES) g_rowstart[i] = incl - v;
    if (tid == 1023) g_bsum[b] = incl;
}

__global__ void scan2_kernel() {
    __shared__ int t0;
    int tid = threadIdx.x, lane = tid & 31, wp = tid >> 5;
    int v = (tid < SCAN_NB) ? g_bsum[tid] : 0;
    int x = v;
#pragma unroll
    for (int off = 1; off < 32; off <<= 1) {
        int y = __shfl_up_sync(0xffffffffu, x, off);
        if (lane >= off) x += y;
    }
    if (wp == 0 && lane == 31) t0 = x;
    __syncthreads();
    int incl = x + (wp ? t0 : 0);
    if (tid < SCAN_NB) g_boff[tid] = incl - v;
    if (tid == SCAN_NB - 1) g_rowstart[N_NODES] = incl;
}

__global__ __launch_bounds__(1024) void scan3_kernel() {
    int i = blockIdx.x * 1024 + threadIdx.x;
    if (i < N_NODES) g_rowstart[i] += g_boff[blockIdx.x];
}

__global__ void fill_kernel(const int* __restrict__ src, const int* __restrict__ dst) {
    int e = blockIdx.x * blockDim.x + threadIdx.x;
    if (e < N_EDGES) {
        int s = src[e];
        int p = atomicAdd(&g_cursor[s], 1);
        g_csr_dst[g_rowstart[s] + p] = dst[e];
    }
}

// ---------------- single-pass softmax + aggregation (fp16 gather) ------------
__global__ __launch_bounds__(256) void agg_kernel(float* __restrict__ out) {
    int n   = blockIdx.x;
    int tid = threadIdx.x;
    int rs  = g_rowstart[n];
    int deg = g_rowstart[n + 1] - rs;

    __shared__ float s_as[N_HEADS];
    __shared__ float s_inv[N_HEADS];
    __shared__ int   s_d[32];
    __shared__ float s_att[32 * N_HEADS];
    __shared__ float s_part[8][9];

    int w  = tid >> 5, l = tid & 31;
    int ii = tid >> 3, h = tid & 7;       // edge-slot, head (coalesced alpha_d)
    int hh = tid >> 5;                    // head for output cols [tid*2, tid*2+1]

    if (tid < N_HEADS) s_as[tid] = g_alpha_s[n * N_HEADS + tid];
    __syncthreads();
    float as_h = s_as[h];

    float2 acc = make_float2(0.f, 0.f);
    float esum = 0.f;
    const __half2* fh = (const __half2*)g_feath;

    for (int c = 0; c < deg; c += 32) {
        int len = min(32, deg - c);
        __syncthreads();
        if (tid < len) s_d[tid] = g_csr_dst[rs + c + tid];
        __syncthreads();
        if (ii < len) {
            int d = s_d[ii];
            float v = as_h + g_alpha_d[d * N_HEADS + h];
            v = (v > 0.f) ? v : LRELU_ALPHA * v;
            float e = __expf(v);
            s_att[ii * 8 + h] = e;
            esum += e;
        }
        __syncthreads();
        for (int i = 0; i < len; i++) {
            int d = s_d[i];
            float a = s_att[i * 8 + hh];
            float2 f = __half22float2(fh[(long)d * (FEAT_DIM / 2) + tid]);
            acc.x = fmaf(a, f.x, acc.x);
            acc.y = fmaf(a, f.y, acc.y);
        }
    }

    esum += __shfl_xor_sync(0xffffffffu, esum, 8);
    esum += __shfl_xor_sync(0xffffffffu, esum, 16);
    if (l < 8) s_part[w][l] = esum;
    __syncthreads();
    if (tid < N_HEADS) {
        float s = 0.f;
#pragma unroll
        for (int ww = 0; ww < 8; ww++) s += s_part[ww][tid];
        s_inv[tid] = (deg > 0) ? (1.0f / s) : 0.f;
    }
    __syncthreads();

    float inv = s_inv[hh];
    float2* o2 = (float2*)out;
    o2[(long)n * (FEAT_DIM / 2) + tid] =
        make_float2(fmaxf(acc.x * inv, 0.f), fmaxf(acc.y * inv, 0.f));
}

// ---------------- launch: fork/join two branches inside the capture -----------
extern "C" void kernel_launch(void* const* d_in, const int* in_sizes, int n_in,
                              void* d_out, int out_size) {
    const float* x     = (const float*)d_in[0];
    const float* W     = (const float*)d_in[1];
    const float* att_w = (const float*)d_in[2];
    const int*   src   = (const int*)d_in[3];
    const int*   dst   = (const int*)d_in[4];
    float* out = (float*)d_out;

    static cudaStream_t s2 = nullptr;
    static cudaEvent_t  ev0 = nullptr, ev1 = nullptr;
    if (s2 == nullptr) {                       // host-side resources only
        cudaStreamCreateWithFlags(&s2, cudaStreamNonBlocking);
        cudaEventCreateWithFlags(&ev0, cudaEventDisableTiming);
        cudaEventCreateWithFlags(&ev1, cudaEventDisableTiming);
    }

    cudaFuncSetAttribute(gemm_fp16_kernel,
                         cudaFuncAttributeMaxDynamicSharedMemorySize, GEMM_SMEM_BYTES);

    // fork: branch B (CSR build) on s2, branch A (prep+gemm) on main stream
    cudaEventRecord(ev0, 0);
    cudaStreamWaitEvent(s2, ev0, 0);

    prep_kernel<<<1024, 256>>>(x, W);                          // A (launch 1)
    zero_csr_kernel<<<256, 256, 0, s2>>>();                    // B (launch 2)
    count_kernel<<<(N_EDGES + 255) / 256, 256, 0, s2>>>(src);  // B (launch 3)
    gemm_fp16_kernel<<<dim3(FEAT_DIM / GEMM_BN, (N_NODES + GEMM_BM - 1) / GEMM_BM),
                      256, GEMM_SMEM_BYTES>>>(att_w);          // A (launch 4: ncu)
    scan1_kernel<<<SCAN_NB, 1024, 0, s2>>>();                  // B
    scan2_kernel<<<1, 64, 0, s2>>>();                          // B
    scan3_kernel<<<SCAN_NB, 1024, 0, s2>>>();                  // B
    fill_kernel<<<(N_EDGES + 255) / 256, 256, 0, s2>>>(src, dst);  // B

    // join: agg needs both branches
    cudaEventRecord(ev1, s2);
    cudaStreamWaitEvent(0, ev1, 0);
    agg_kernel<<<N_NODES, 256>>>(out);
}